// round 15
// baseline (speedup 1.0000x reference)
#include <cuda_runtime.h>
#include <cuda_fp16.h>
#include <mma.h>
#include <math.h>

using namespace nvcuda;

// Problem constants
#define NB    8
#define C     528
#define T     16
#define HH    32
#define WW    32
#define R     1024
#define OUTB  8
#define SR    2
#define SCALE (1.0f/16.0f)

#define NJ     128           // layer-1 width
#define NPX    (NB*HH*WW)    // 8192 pixels
#define MAXSUP 144

// NHWC feature scratch fp16: [pixel][c]
__device__ __half g_feat_h[NPX * C];
// W1 in fp16: [c][j]
__device__ __half g_W1h[C * NJ];
// projected features fp16: [pixel][j]
__device__ __half g_proj[NPX * NJ];

// ---------------------------------------------------------------------------
// Kernel 1: temporal mean + NCHW -> NHWC transpose, float4 loads (R11 best).
// grid: (NB*HH, 17), block: 256. cchunk==16 blocks also convert W1 -> fp16.
// ---------------------------------------------------------------------------
__global__ __launch_bounds__(256)
void mean_t_transpose_kernel(const float* __restrict__ x,
                             const float* __restrict__ W1)
{
    __shared__ float tile[32][37];

    const int bid = blockIdx.x;        // b*32 + y
    const int b   = bid >> 5;
    const int y   = bid & 31;
    const int cchunk = blockIdx.y;

    const int tid = threadIdx.x;
    const int xq  = tid & 7;
    const int cl  = tid >> 3;

    const int c = cchunk * 32 + cl;
    if (c < C) {
        const float4* p = (const float4*)
            (x + (((size_t)(b * C + c) * T) * HH + y) * WW + xq * 4);
        float4 s0 = make_float4(0.f, 0.f, 0.f, 0.f);
        float4 s1 = make_float4(0.f, 0.f, 0.f, 0.f);
        #pragma unroll
        for (int t = 0; t < T; t += 2) {
            const float4 v0 = __ldcs(p + (size_t)t       * (HH * WW / 4));
            const float4 v1 = __ldcs(p + (size_t)(t + 1) * (HH * WW / 4));
            s0.x += v0.x; s0.y += v0.y; s0.z += v0.z; s0.w += v0.w;
            s1.x += v1.x; s1.y += v1.y; s1.z += v1.z; s1.w += v1.w;
        }
        const int xb = xq * 4;
        tile[cl][xb + 0] = (s0.x + s1.x) * (1.0f / T);
        tile[cl][xb + 1] = (s0.y + s1.y) * (1.0f / T);
        tile[cl][xb + 2] = (s0.z + s1.z) * (1.0f / T);
        tile[cl][xb + 3] = (s0.w + s1.w) * (1.0f / T);
    }

    // under-utilized chunk-16 blocks also convert W1 to fp16 (67584 elems)
    if (cchunk == 16) {
        const int base = bid * 264;          // 256 blocks x 264 = 67584
        #pragma unroll
        for (int i = tid; i < 264; i += 256)
            g_W1h[base + i] = __float2half(W1[base + i]);
    }
    __syncthreads();

    const int cw = tid & 31;
    const int xw = tid >> 5;
    const int c2 = cchunk * 32 + cw;
    if (c2 < C) {
        #pragma unroll
        for (int xs = 0; xs < 4; xs++) {
            const int xx = xs * 8 + xw;
            g_feat_h[(((size_t)(b * HH + y)) * WW + xx) * C + c2] =
                __float2half(tile[cw][xx]);
        }
    }
}

// ---------------------------------------------------------------------------
// Kernel 2: projection GEMM proj[8192,128] = feat[8192,528] @ W1[528,128]
// wmma m16n16k16, fp16 inputs, fp32 accum. grid: 128, block: 256 (8 warps).
// Block tile 64x128: warps 4x2, each warp 16x64 (4 accum frags), K = 33 steps.
// ---------------------------------------------------------------------------
__global__ __launch_bounds__(256)
void proj_kernel()
{
    __shared__ float sOut[64][128];

    const int tid  = threadIdx.x;
    const int wid  = tid >> 5;
    const int wr   = wid & 3;            // warp row 0..3 (16 rows each)
    const int wc   = wid >> 2;           // warp col 0..1 (64 cols each)
    const int row0 = blockIdx.x * 64 + wr * 16;
    const int col0 = wc * 64;

    wmma::fragment<wmma::accumulator, 16, 16, 16, float> acc[4];
    #pragma unroll
    for (int i = 0; i < 4; i++) wmma::fill_fragment(acc[i], 0.0f);

    for (int k = 0; k < C; k += 16) {
        wmma::fragment<wmma::matrix_a, 16, 16, 16, __half, wmma::row_major> a;
        wmma::load_matrix_sync(a, g_feat_h + (size_t)row0 * C + k, C);
        #pragma unroll
        for (int i = 0; i < 4; i++) {
            wmma::fragment<wmma::matrix_b, 16, 16, 16, __half, wmma::row_major> bfr;
            wmma::load_matrix_sync(bfr, g_W1h + (size_t)k * NJ + col0 + i * 16, NJ);
            wmma::mma_sync(acc[i], a, bfr, acc[i]);
        }
    }

    #pragma unroll
    for (int i = 0; i < 4; i++)
        wmma::store_matrix_sync(&sOut[wr * 16][col0 + i * 16], acc[i], NJ,
                                wmma::mem_row_major);
    __syncthreads();

    // convert to fp16 global (half2 stores)
    const int row_base = blockIdx.x * 64;
    #pragma unroll
    for (int u = tid; u < 64 * 64; u += 256) {
        const int r  = u >> 6;
        const int p2 = u & 63;           // half2 index within row
        const __half2 h = __floats2half2_rn(sOut[r][p2 * 2], sOut[r][p2 * 2 + 1]);
        ((__half2*)g_proj)[(size_t)(row_base + r) * 64 + p2] = h;
    }
}

// ---------------------------------------------------------------------------
// Kernel 3: ROI pooling in projected 128-dim space + MLP tail.
// grid: R, block: 256 = 16 support-slices x 16 channel-groups (uint4 = 8 ch).
// ---------------------------------------------------------------------------
__global__ __launch_bounds__(256)
void roi_head_kernel(const float* __restrict__ bbox,
                     const float* __restrict__ b1,
                     const float* __restrict__ W2, const float* __restrict__ b2,
                     const float* __restrict__ W3, const float* __restrict__ b3,
                     float* __restrict__ out)
{
    __shared__ float sAx[32], sAy[32];
    __shared__ int   sB, sXlo, sNx, sYlo, sNy, sN;
    __shared__ int   sOff[MAXSUP];      // pixel offset in uint4 units (pixel*16)
    __shared__ float sW[MAXSUP];
    __shared__ float sPar[16][16][8];   // [slice][lane][sub-channel] (8 KB)
    __shared__ float sH1[NJ];
    __shared__ float sPart2[4][32];
    __shared__ float sH2[32];

    const int tid = threadIdx.x;
    const int roi = blockIdx.x;

    // Phase A1: per-bin axis weights (warp0 = x, warp1 = y), deterministic
    if (tid < 64) {
        const int axis = tid >> 5;
        const int bin  = tid & 31;
        const float* bb = bbox + roi * 5;
        if (tid == 0) sB = (int)bb[0];

        const float lo_c = bb[1 + axis] * SCALE - 0.5f;
        const float hi_c = bb[3 + axis] * SCALE - 0.5f;
        const float step = (hi_c - lo_c) * (1.0f / (OUTB * SR));

        float w = 0.f;
        #pragma unroll
        for (int s = 0; s < 16; s++) {
            const float v = lo_c + ((float)s + 0.5f) * step;
            const bool valid = (v >= -1.0f) && (v <= 32.0f);
            float vc   = fminf(fmaxf(v, 0.0f), 31.0f);
            float lof  = floorf(vc);
            float frac = vc - lof;
            int ilo = (int)lof;
            int ihi = min(ilo + 1, 31);
            if (valid) {
                if (ilo == bin) w += 1.0f - frac;
                if (ihi == bin) w += frac;
            }
        }
        if (axis) sAy[bin] = w; else sAx[bin] = w;

        unsigned m = __ballot_sync(0xFFFFFFFF, w != 0.f);
        if (bin == 0) {
            int lo, n;
            if (m == 0u) { lo = 0; n = 0; }
            else { lo = __ffs(m) - 1; n = (31 - __clz(m)) - lo + 1; }
            if (axis) { sYlo = lo; sNy = n; }
            else      { sXlo = lo; sNx = n; }
        }
    }
    __syncthreads();

    // Phase A2: flatten support into (offset, weight) list
    {
        const int nx = sNx, ny = sNy;
        int n = nx * ny;
        if (n > MAXSUP) n = MAXSUP;
        if (tid == 0) sN = n;
        const int pxbase = sB * (HH * WW);
        for (int i = tid; i < n; i += 256) {
            const int iy = i / nx;
            const int ix = i - iy * nx;
            const int y  = sYlo + iy;
            const int xp = sXlo + ix;
            sOff[i] = (pxbase + y * WW + xp) * (NJ / 8);
            sW[i]   = sAy[y] * sAx[xp] * (1.0f / 256.0f);
        }
    }
    __syncthreads();

    // Phase B: gather in 128-dim space. slice q takes i = q, q+16, ...
    {
        const int lane = tid & 15;       // uint4 channel group (8 halves)
        const int q    = tid >> 4;       // support slice 0..15
        const int n    = sN;
        const uint4* base = (const uint4*)g_proj + lane;

        float a[8];
        #pragma unroll
        for (int s = 0; s < 8; s++) a[s] = 0.f;

        for (int i = q; i < n; i += 16) {
            const float w   = sW[i];
            const uint4 raw = base[sOff[i]];
            const float2 f0 = __half22float2(*(const __half2*)&raw.x);
            const float2 f1 = __half22float2(*(const __half2*)&raw.y);
            const float2 f2 = __half22float2(*(const __half2*)&raw.z);
            const float2 f3 = __half22float2(*(const __half2*)&raw.w);
            a[0] = fmaf(w, f0.x, a[0]); a[1] = fmaf(w, f0.y, a[1]);
            a[2] = fmaf(w, f1.x, a[2]); a[3] = fmaf(w, f1.y, a[3]);
            a[4] = fmaf(w, f2.x, a[4]); a[5] = fmaf(w, f2.y, a[5]);
            a[6] = fmaf(w, f3.x, a[6]); a[7] = fmaf(w, f3.y, a[7]);
        }
        #pragma unroll
        for (int s = 0; s < 8; s++) sPar[q][lane][s] = a[s];
    }
    __syncthreads();

    // Phase C: reduce 16 slices (fixed order) + bias + relu -> h1
    if (tid < NJ) {
        const int lane = tid >> 3;
        const int sub  = tid & 7;
        float v = 0.f;
        #pragma unroll
        for (int q = 0; q < 16; q++)
            v += sPar[q][lane][sub];
        sH1[tid] = fmaxf(v + b1[tid], 0.f);
    }
    __syncthreads();

    // Layer 2: 128 threads = 4 k-parts x 32 outputs
    if (tid < 128) {
        const int part = tid >> 5;
        const int j2   = tid & 31;
        const int k0 = part * 32;
        float a0 = 0.f, a1 = 0.f;
        #pragma unroll
        for (int k = k0; k < k0 + 32; k += 2) {
            a0 = fmaf(sH1[k],     W2[(k)     * 32 + j2], a0);
            a1 = fmaf(sH1[k + 1], W2[(k + 1) * 32 + j2], a1);
        }
        sPart2[part][j2] = a0 + a1;
    }
    __syncthreads();
    if (tid < 32) {
        sH2[tid] = (sPart2[0][tid] + sPart2[1][tid])
                 + (sPart2[2][tid] + sPart2[3][tid]) + b2[tid];
    }
    __syncthreads();

    // Layer 3 + sigmoid
    if (tid < 32) {
        float v = sH2[tid] * W3[tid];
        #pragma unroll
        for (int off = 16; off > 0; off >>= 1)
            v += __shfl_xor_sync(0xFFFFFFFF, v, off);
        if (tid == 0)
            out[roi] = 1.0f / (1.0f + expf(-(v + b3[0])));
    }
}

// ---------------------------------------------------------------------------
extern "C" void kernel_launch(void* const* d_in, const int* in_sizes, int n_in,
                              void* d_out, int out_size)
{
    const float* x    = (const float*)d_in[0];
    const float* bbox = (const float*)d_in[1];
    const float* W1   = (const float*)d_in[2];
    const float* b1   = (const float*)d_in[3];
    const float* W2   = (const float*)d_in[4];
    const float* b2   = (const float*)d_in[5];
    const float* W3   = (const float*)d_in[6];
    const float* b3   = (const float*)d_in[7];
    float* out = (float*)d_out;

    dim3 g1(NB * HH, 17);
    mean_t_transpose_kernel<<<g1, 256>>>(x, W1);

    proj_kernel<<<NPX / 64, 256>>>();

    roi_head_kernel<<<R, 256>>>(bbox, b1, W2, b2, W3, b3, out);
}